// round 11
// baseline (speedup 1.0000x reference)
#include <cuda_runtime.h>

// Antialiased bilinear (triangle) 4x downsample — vertical-first separable,
// bare-LDG load path (no predication, immediate offsets on interior warps).
// x: (2048,6,128,96) f32 -> out: (2048,6,32,24) f32 (= (B,6,768))
//
// Block = 8 warps = HALF an image (grid 24576). Warp owns output rows
// or0, or0+1; hoists its 12 input rows (LDG.128; lanes>=24 alias lane 23,
// harmless broadcast). Vertical 8-tap collapses 12 rows -> 2 packed rows
// (no shuffles), then horizontal 8-tap on the 2 rows via partial-sum
// exchange (2 shuffles/row). OOB taps dropped + renormalized == jax
// antialias; edge correction is exact by linearity.

#define IN_H  128
#define IN_W  96
#define OUT_H 32
#define OUT_W 24
#define BLOCKS (12288 * 2)

__global__ __launch_bounds__(256, 4)
void resize_aa_kernel(const float* __restrict__ x, float* __restrict__ out)
{
    const int lane = threadIdx.x & 31;
    const int warp = threadIdx.x >> 5;              // 0..7
    const size_t img  = blockIdx.x >> 1;
    const int   half  = blockIdx.x & 1;
    const bool  act   = lane < OUT_W;

    const float m0    = (lane == 0)          ? 0.f : 1.f;   // mask shfl_up garbage
    const float m23   = (lane == OUT_W - 1)  ? 0.f : 1.f;   // mask shfl_down garbage
    const float inv_s = (lane == 0 || lane == OUT_W - 1) ? (1.f / 3.5f) : 0.25f;

    const int or0   = half * 16 + 2 * warp;         // first of 2 output rows
    const int rbase = 4 * or0 - 2;                  // first input row needed

    const int lload = lane < OUT_W ? lane : (OUT_W - 1);    // lanes>=24 alias lane 23
    const float4* __restrict__ base =
        (const float4*)(x + img * (size_t)(IN_H * IN_W)) + lload;   // + r*24 per row

    // ---- PHASE 1: hoist 12 row loads ----
    float4 v[12];
    if (rbase >= 0 && rbase + 11 < IN_H) {
        // interior warps (14/16): single base, compile-time 384B offsets
        const float4* __restrict__ p = base + (size_t)rbase * (IN_W / 4);
#pragma unroll
        for (int i = 0; i < 12; ++i)
            v[i] = p[i * (IN_W / 4)];
    } else {
        // edge warps: clamped rows (their contribution corrected below)
#pragma unroll
        for (int i = 0; i < 12; ++i) {
            int r = rbase + i;
            r = r < 0 ? 0 : (r > IN_H - 1 ? IN_H - 1 : r);
            v[i] = base[(size_t)r * (IN_W / 4)];
        }
    }

    // ---- PHASE 2: vertical 8-tap on raw columns (12 rows -> 2 rows) ----
    // raw taps tri(k) = {.125,.375,.625,.875,.875,.625,.375,.125}
    float4 a0 = make_float4(0.f, 0.f, 0.f, 0.f);
    float4 a1 = make_float4(0.f, 0.f, 0.f, 0.f);
#pragma unroll
    for (int i = 0; i < 12; ++i) {
        if (i < 8) {
            const float wv = 1.f - fabsf((float)i - 3.5f) * 0.25f;        // imm
            a0.x = fmaf(v[i].x, wv, a0.x);
            a0.y = fmaf(v[i].y, wv, a0.y);
            a0.z = fmaf(v[i].z, wv, a0.z);
            a0.w = fmaf(v[i].w, wv, a0.w);
        }
        if (i >= 4) {
            const float wv = 1.f - fabsf((float)(i - 4) - 3.5f) * 0.25f;  // imm
            a1.x = fmaf(v[i].x, wv, a1.x);
            a1.y = fmaf(v[i].y, wv, a1.y);
            a1.z = fmaf(v[i].z, wv, a1.z);
            a1.w = fmaf(v[i].w, wv, a1.w);
        }
    }

    // ---- vertical edge correction (exact, uniform per warp) ----
    float n0 = 0.25f, n1 = 0.25f;                    // vertical renorm factors
    if (or0 == 0) {                                  // rows -2,-1 were dupes of row 0
        a0.x -= fmaf(v[0].x, 0.125f, v[1].x * 0.375f);
        a0.y -= fmaf(v[0].y, 0.125f, v[1].y * 0.375f);
        a0.z -= fmaf(v[0].z, 0.125f, v[1].z * 0.375f);
        a0.w -= fmaf(v[0].w, 0.125f, v[1].w * 0.375f);
        n0 = 1.f / 3.5f;
    }
    if (or0 + 1 == OUT_H - 1) {                      // rows 128,129 dupes of 127
        a1.x -= fmaf(v[10].x, 0.375f, v[11].x * 0.125f);
        a1.y -= fmaf(v[10].y, 0.375f, v[11].y * 0.125f);
        a1.z -= fmaf(v[10].z, 0.375f, v[11].z * 0.125f);
        a1.w -= fmaf(v[10].w, 0.375f, v[11].w * 0.125f);
        n1 = 1.f / 3.5f;
    }

    // ---- PHASE 3: horizontal 8-tap on the 2 collapsed rows ----
    float* __restrict__ op = out + img * (size_t)(OUT_H * OUT_W);
#pragma unroll
    for (int o = 0; o < 2; ++o) {
        const float4 a = o ? a1 : a0;
        const float  nv = o ? n1 : n0;

        float pR = a.z * 0.125f; pR = fmaf(a.w, 0.375f, pR);   // -> lane+1
        float pL = a.x * 0.375f; pL = fmaf(a.y, 0.125f, pL);   // -> lane-1
        const float rcvU = __shfl_up_sync(0xffffffffu, pR, 1);
        const float rcvD = __shfl_down_sync(0xffffffffu, pL, 1);

        float h;
        h = a.x * 0.625f;
        h = fmaf(a.y, 0.875f, h);
        h = fmaf(a.z, 0.875f, h);
        h = fmaf(a.w, 0.625f, h);
        h = fmaf(rcvD, m23, h);             // lane 23: neighbor is aliased garbage
        h = fmaf(rcvU, m0,  h);             // lane 0: up-shuffle self garbage

        if (act) op[(or0 + o) * OUT_W + lane] = h * (inv_s * nv);
    }
}

extern "C" void kernel_launch(void* const* d_in, const int* in_sizes, int n_in,
                              void* d_out, int out_size)
{
    const float* x = (const float*)d_in[0];   // (2048,6,128,96) f32; d_in[1] unused
    float* out = (float*)d_out;               // (2048,6,768) f32
    resize_aa_kernel<<<BLOCKS, 256>>>(x, out);
}

// round 14
// speedup vs baseline: 1.0030x; 1.0030x over previous
#include <cuda_runtime.h>

// Antialiased bilinear (triangle) 4x downsample — vertical-first separable.
// x: (2048,6,128,96) f32 -> out: (2048,6,32,24) f32 (= (B,6,768))
//
// Block = 8 warps = HALF an image (grid 24576). Warp owns output rows
// or0, or0+1; hoists its 12 input rows (LDG.128, unconditional: lanes>=24
// alias lane 23's address — same 128B line, no extra sectors, no predication).
// Vertical 8-tap collapses 12 rows -> 2 packed float4 rows (no shuffles),
// then horizontal 8-tap on the 2 rows via partial-sum exchange
// (2 shuffles/row). OOB taps dropped + renormalized == jax antialias;
// clamped-row contributions removed exactly by linearity. Output uses
// streaming stores (never re-read).

#define IN_H  128
#define IN_W  96
#define OUT_H 32
#define OUT_W 24
#define BLOCKS (12288 * 2)

__global__ __launch_bounds__(256, 4)
void resize_aa_kernel(const float* __restrict__ x, float* __restrict__ out)
{
    const int lane = threadIdx.x & 31;
    const int warp = threadIdx.x >> 5;              // 0..7
    const size_t img  = blockIdx.x >> 1;
    const int   half  = blockIdx.x & 1;
    const bool  act   = lane < OUT_W;

    const float m0    = (lane == 0)         ? 0.f : 1.f;    // mask shfl_up garbage
    const float m23   = (lane == OUT_W - 1) ? 0.f : 1.f;    // mask shfl_down garbage
    const float inv_s = (lane == 0 || lane == OUT_W - 1) ? (1.f / 3.5f) : 0.25f;

    const int or0   = half * 16 + 2 * warp;         // first of 2 output rows
    const int rbase = 4 * or0 - 2;                  // first input row needed

    const int lload = act ? lane : (OUT_W - 1);     // lanes>=24 alias lane 23
    const float4* __restrict__ base =
        (const float4*)(x + img * (size_t)(IN_H * IN_W)) + lload;

    // ---- PHASE 1: hoist all 12 row loads (independent LDG.128s, no branch) ----
    float4 v[12];
#pragma unroll
    for (int i = 0; i < 12; ++i) {
        int r = rbase + i;
        r = r < 0 ? 0 : (r > IN_H - 1 ? IN_H - 1 : r);   // IMNMX clamp (fixed below)
        v[i] = base[(size_t)r * (IN_W / 4)];
    }

    // ---- PHASE 2: vertical 8-tap on raw columns (12 rows -> 2 rows) ----
    // raw taps tri(k) = {.125,.375,.625,.875,.875,.625,.375,.125}
    float4 a0 = make_float4(0.f, 0.f, 0.f, 0.f);
    float4 a1 = make_float4(0.f, 0.f, 0.f, 0.f);
#pragma unroll
    for (int i = 0; i < 12; ++i) {
        if (i < 8) {
            const float wv = 1.f - fabsf((float)i - 3.5f) * 0.25f;        // imm
            a0.x = fmaf(v[i].x, wv, a0.x);
            a0.y = fmaf(v[i].y, wv, a0.y);
            a0.z = fmaf(v[i].z, wv, a0.z);
            a0.w = fmaf(v[i].w, wv, a0.w);
        }
        if (i >= 4) {
            const float wv = 1.f - fabsf((float)(i - 4) - 3.5f) * 0.25f;  // imm
            a1.x = fmaf(v[i].x, wv, a1.x);
            a1.y = fmaf(v[i].y, wv, a1.y);
            a1.z = fmaf(v[i].z, wv, a1.z);
            a1.w = fmaf(v[i].w, wv, a1.w);
        }
    }

    // ---- vertical edge correction (exact, uniform per warp) ----
    float n0 = 0.25f, n1 = 0.25f;                    // vertical renorm factors
    if (or0 == 0) {                                  // rows -2,-1 were dupes of row 0
        a0.x -= fmaf(v[0].x, 0.125f, v[1].x * 0.375f);
        a0.y -= fmaf(v[0].y, 0.125f, v[1].y * 0.375f);
        a0.z -= fmaf(v[0].z, 0.125f, v[1].z * 0.375f);
        a0.w -= fmaf(v[0].w, 0.125f, v[1].w * 0.375f);
        n0 = 1.f / 3.5f;
    }
    if (or0 + 1 == OUT_H - 1) {                      // rows 128,129 dupes of 127
        a1.x -= fmaf(v[10].x, 0.375f, v[11].x * 0.125f);
        a1.y -= fmaf(v[10].y, 0.375f, v[11].y * 0.125f);
        a1.z -= fmaf(v[10].z, 0.375f, v[11].z * 0.125f);
        a1.w -= fmaf(v[10].w, 0.375f, v[11].w * 0.125f);
        n1 = 1.f / 3.5f;
    }

    // ---- PHASE 3: horizontal 8-tap on the 2 collapsed rows ----
    float* __restrict__ op = out + img * (size_t)(OUT_H * OUT_W);
#pragma unroll
    for (int o = 0; o < 2; ++o) {
        const float4 a = o ? a1 : a0;
        const float  nv = o ? n1 : n0;

        float pR = a.z * 0.125f; pR = fmaf(a.w, 0.375f, pR);   // -> lane+1
        float pL = a.x * 0.375f; pL = fmaf(a.y, 0.125f, pL);   // -> lane-1
        const float rcvU = __shfl_up_sync(0xffffffffu, pR, 1);
        const float rcvD = __shfl_down_sync(0xffffffffu, pL, 1);

        float h;
        h = a.x * 0.625f;
        h = fmaf(a.y, 0.875f, h);
        h = fmaf(a.z, 0.875f, h);
        h = fmaf(a.w, 0.625f, h);
        h = fmaf(rcvD, m23, h);             // lane 23: neighbor holds aliased garbage
        h = fmaf(rcvU, m0,  h);             // lane 0: up-shuffle self garbage

        if (act)
            __stcs(op + (or0 + o) * OUT_W + lane, h * (inv_s * nv));  // streaming store
    }
}

extern "C" void kernel_launch(void* const* d_in, const int* in_sizes, int n_in,
                              void* d_out, int out_size)
{
    const float* x = (const float*)d_in[0];   // (2048,6,128,96) f32; d_in[1] unused
    float* out = (float*)d_out;               // (2048,6,768) f32
    resize_aa_kernel<<<BLOCKS, 256>>>(x, out);
}